// round 5
// baseline (speedup 1.0000x reference)
#include <cuda_runtime.h>
#include <cuda_fp16.h>

#define BB 256   // batch
#define SS 256   // seq len / steps
#define DD 128   // decoder dim
#define GG 512   // 4*D gates

// fp16x2-packed LSTM hidden weights, warp-coalesced block layout:
// uint4 block (j,u): j=0..15 (k-range [8j,8j+8)), u=0..511 (gate).
// word m of block = half2{ W_hh[u][8j+2m], W_hh[u][8j+2m+1] }.
// flat uint index = (j*512 + u)*4 + m.  Total 128 KB -> L1-resident.
__device__ __align__(16) unsigned int g_Wpack[32768];
__device__ float g_w1sum[SS];
__device__ float g_bias[GG];

__device__ __forceinline__ float tanh_fast(float x) {
    float y;
    asm("tanh.approx.f32 %0, %1;" : "=f"(y) : "f"(x));
    return y;
}
__device__ __forceinline__ float sigmoid_fast(float x) {
    return fmaf(tanh_fast(0.5f * x), 0.5f, 0.5f);
}
__device__ __forceinline__ unsigned long long pack2(float a, float b) {
    unsigned long long r;
    asm("mov.b64 %0, {%1,%2};" : "=l"(r) : "f"(a), "f"(b));
    return r;
}

// ---------------------------------------------------------------------------
// Prep kernel: pack W_hh to fp16 blocks, row-sum W1_w, fuse biases. One-time.
// ---------------------------------------------------------------------------
__global__ void prep_kernel(const float* __restrict__ W1_w,
                            const float* __restrict__ W_hh,
                            const float* __restrict__ b_ih,
                            const float* __restrict__ b_hh) {
    int blk = blockIdx.x;
    int t = threadIdx.x;
    if (blk < 128) {
        int idx = blk * 256 + t;          // 0..32767
        int j = idx >> 11;                // k-block 0..15
        int u = (idx >> 2) & 511;         // gate
        int m = idx & 3;
        int k0 = 8 * j + 2 * m;
        __half2 v = __halves2half2(__float2half_rn(W_hh[u * DD + k0]),
                                   __float2half_rn(W_hh[u * DD + k0 + 1]));
        g_Wpack[idx] = *(unsigned int*)&v;
    } else {
        int lane = t & 31, w = t >> 5;
        for (int r = 0; r < 32; r++) {
            int s = w * 32 + r;
            float acc = 0.f;
            #pragma unroll
            for (int i = 0; i < 8; i++) acc += W1_w[s * SS + lane + 32 * i];
            #pragma unroll
            for (int off = 16; off; off >>= 1)
                acc += __shfl_xor_sync(0xffffffffu, acc, off);
            if (lane == 0) g_w1sum[s] = acc;
        }
        g_bias[t]       = b_ih[t]       + b_hh[t];
        g_bias[t + 256] = b_ih[t + 256] + b_hh[t + 256];
    }
}

// ---------------------------------------------------------------------------
// Main kernel: one CTA per batch element, 512 threads, 256 LSTM steps.
// Attention split 4-ways over s (quarters); LSTM: one gate per thread.
// ---------------------------------------------------------------------------
__global__ __launch_bounds__(512, 2)
void decoder_kernel(const float* __restrict__ enc,   // [B,S,E]
                    const float* __restrict__ W1_b,  // [S]
                    const float* __restrict__ W2_w,  // [S,2S]
                    const float* __restrict__ W2_b,  // [S]
                    const float* __restrict__ W_ih,  // [4D,E]
                    float* __restrict__ out)         // [S,B,D]
{
    __shared__ __align__(16) float4 sAC[128];    // pair p: {a(2p),a(2p+1),c(2p),c(2p+1)}
    __shared__ __align__(16) float4 sE[128];     // pair p: {e0(2p),e0(2p+1),e1(2p),e1(2p+1)}
    __shared__ __align__(16) float  ebuf[2 * SS];
    __shared__ float a_st[SS];
    __shared__ __align__(16) float4 red3[3 * DD];  // quarters 1..3 partials {Z,n0,n1,_}
    __shared__ float gates_s[GG];
    __shared__ __align__(16) float h_s[DD];
    __shared__ float c_s[DD];
    __shared__ __align__(16) float2 wred[4];

    const int b = blockIdx.x;
    const int t = threadIdx.x;       // 0..511
    const int lane = t & 31;
    const int warp = t >> 5;

    // ---- per-b init ----
    ebuf[t] = enc[b * (2 * SS) + t];
    if (t < DD) { h_s[t] = 0.f; c_s[t] = 0.f; }
    __syncthreads();

    // a[s] = encflat . W2_w[s,:] + W2_b[s] + W1_b[s]; 16 warps x 16 rows
    {
        const float4* W2w4 = (const float4*)W2_w;
        const float4* e4   = (const float4*)ebuf;
        for (int r = 0; r < 16; r++) {
            int s = warp * 16 + r;
            float acc = 0.f;
            #pragma unroll
            for (int i = 0; i < 4; i++) {
                float4 wv = W2w4[s * 128 + lane + 32 * i];
                float4 ev = e4[lane + 32 * i];
                acc += wv.x * ev.x + wv.y * ev.y + wv.z * ev.z + wv.w * ev.w;
            }
            #pragma unroll
            for (int off = 16; off; off >>= 1)
                acc += __shfl_xor_sync(0xffffffffu, acc, off);
            if (lane == 0) a_st[s] = acc + W2_b[s] + W1_b[s];
        }
    }
    __syncthreads();
    if (t < 128) {
        int p = t;
        sAC[p] = make_float4(a_st[2 * p], a_st[2 * p + 1],
                             g_w1sum[2 * p], g_w1sum[2 * p + 1]);
        sE[p]  = make_float4(ebuf[4 * p], ebuf[4 * p + 2],
                             ebuf[4 * p + 1], ebuf[4 * p + 3]);
    }
    __syncthreads();

    // Degree-4 minimax-ish poly for exp(t), t in [-1,1], abs err ~6e-4
    const unsigned long long P4 = pack2(0.04379392f, 0.04379392f);
    const unsigned long long P3 = pack2(0.17734740f, 0.17734740f);
    const unsigned long long P2 = pack2(0.49919676f, 0.49919676f);
    const unsigned long long P1 = pack2(0.99730766f, 0.99730766f);
    const unsigned long long P0 = pack2(1.00004478f, 1.00004478f);

    // thread roles
    const int d = t & 127;            // attention dim
    const int q = t >> 7;             // s-quarter 0..3 (warp-uniform)
    const float bias = g_bias[t];     // LSTM: one gate per thread
    const float wih0 = W_ih[2 * t + 0];
    const float wih1 = W_ih[2 * t + 1];
    const uint4* Wq4 = ((const uint4*)g_Wpack) + t;   // + j*512 per k-block
    const double2* pAC = ((const double2*)sAC) + q * 32;
    const double2* pE  = ((const double2*)sE)  + q * 32;

    for (int step = 0; step < SS; step++) {
        // ---- Attention: quarter of s, 2 elems/iter, exp via deg-4 Horner ----
        const float hd = h_s[d];
        unsigned long long hd2;
        asm("mov.b64 %0, {%1,%1};" : "=l"(hd2) : "f"(hd));
        unsigned long long Z2 = 0ull, n02 = 0ull, n12 = 0ull;

        #pragma unroll 4
        for (int i = 0; i < 32; i++) {
            double2 acd = pAC[i];               // LDS.128 broadcast
            double2 eed = pE[i];                // LDS.128 broadcast
            unsigned long long ap  = __double_as_longlong(acd.x);
            unsigned long long cp  = __double_as_longlong(acd.y);
            unsigned long long e0p = __double_as_longlong(eed.x);
            unsigned long long e1p = __double_as_longlong(eed.y);
            unsigned long long x2;
            asm("fma.rn.f32x2 %0, %1, %2, %3;" : "=l"(x2) : "l"(hd2), "l"(cp), "l"(ap));
            float x0, x1;
            asm("mov.b64 {%0,%1}, %2;" : "=f"(x0), "=f"(x1) : "l"(x2));
            float t0 = tanh_fast(x0);
            float t1 = tanh_fast(x1);
            unsigned long long t2;
            asm("mov.b64 %0, {%1,%2};" : "=l"(t2) : "f"(t0), "f"(t1));
            unsigned long long p;                // exp(t): 4 packed FFMA
            asm("fma.rn.f32x2 %0, %1, %2, %3;" : "=l"(p) : "l"(P4), "l"(t2), "l"(P3));
            asm("fma.rn.f32x2 %0, %0, %1, %2;" : "+l"(p) : "l"(t2), "l"(P2));
            asm("fma.rn.f32x2 %0, %0, %1, %2;" : "+l"(p) : "l"(t2), "l"(P1));
            asm("fma.rn.f32x2 %0, %0, %1, %2;" : "+l"(p) : "l"(t2), "l"(P0));
            asm("add.rn.f32x2 %0, %0, %1;"     : "+l"(Z2) : "l"(p));
            asm("fma.rn.f32x2 %0, %1, %2, %0;" : "+l"(n02) : "l"(p), "l"(e0p));
            asm("fma.rn.f32x2 %0, %1, %2, %0;" : "+l"(n12) : "l"(p), "l"(e1p));
        }
        float Zl, Zh, a0, a1, b0, b1;
        asm("mov.b64 {%0,%1}, %2;" : "=f"(Zl), "=f"(Zh) : "l"(Z2));
        asm("mov.b64 {%0,%1}, %2;" : "=f"(a0), "=f"(a1) : "l"(n02));
        asm("mov.b64 {%0,%1}, %2;" : "=f"(b0), "=f"(b1) : "l"(n12));
        float Z = Zl + Zh, n0 = a0 + a1, n1 = b0 + b1;

        if (q) red3[(q - 1) * DD + d] = make_float4(Z, n0, n1, 0.f);
        __syncthreads();                             // B1

        if (q == 0) {
            float4 r0q = red3[d];
            float4 r1q = red3[DD + d];
            float4 r2q = red3[2 * DD + d];
            Z  += r0q.x + r1q.x + r2q.x;
            n0 += r0q.y + r1q.y + r2q.y;
            n1 += r0q.z + r1q.z + r2q.z;
            float inv = __fdividef(1.f, Z);
            float cx0 = n0 * inv, cx1 = n1 * inv;
            #pragma unroll
            for (int off = 16; off; off >>= 1) {
                cx0 += __shfl_xor_sync(0xffffffffu, cx0, off);
                cx1 += __shfl_xor_sync(0xffffffffu, cx1, off);
            }
            if (lane == 0) wred[warp] = make_float2(cx0, cx1);
        }
        __syncthreads();                             // B2

        float2 r0 = wred[0], r1 = wred[1], r2 = wred[2], r3 = wred[3];
        const float x0c = (r0.x + r1.x + r2.x + r3.x) * (1.f / 128.f);
        const float x1c = (r0.y + r1.y + r2.y + r3.y) * (1.f / 128.f);

        // ---- LSTM gate dot: one gate per thread, fp16 weights (L1) ----
        float acc = fmaf(x0c, wih0, fmaf(x1c, wih1, bias));
        {
            const float4* h4 = (const float4*)h_s;
            #pragma unroll 4
            for (int j = 0; j < 16; j++) {
                uint4 wr = Wq4[j * 512];            // LDG.128, L1-resident
                float4 hA = h4[2 * j];              // broadcast LDS.128
                float4 hB = h4[2 * j + 1];
                float2 f0 = __half22float2(*(const __half2*)&wr.x);
                float2 f1 = __half22float2(*(const __half2*)&wr.y);
                float2 f2 = __half22float2(*(const __half2*)&wr.z);
                float2 f3 = __half22float2(*(const __half2*)&wr.w);
                acc = fmaf(hA.x, f0.x, acc);
                acc = fmaf(hA.y, f0.y, acc);
                acc = fmaf(hA.z, f1.x, acc);
                acc = fmaf(hA.w, f1.y, acc);
                acc = fmaf(hB.x, f2.x, acc);
                acc = fmaf(hB.y, f2.y, acc);
                acc = fmaf(hB.z, f3.x, acc);
                acc = fmaf(hB.w, f3.y, acc);
            }
        }
        gates_s[t] = acc;
        __syncthreads();                             // B3

        // ---- c/h update + output ----
        if (t < DD) {
            float gi = gates_s[t];
            float gf = gates_s[t + 128];
            float gg = gates_s[t + 256];
            float go = gates_s[t + 384];
            float si = sigmoid_fast(gi);
            float sf = sigmoid_fast(gf);
            float so = sigmoid_fast(go);
            float c = fmaf(sf, c_s[t], si * tanh_fast(gg));
            float h = so * tanh_fast(c);
            c_s[t] = c;
            h_s[t] = h;
            out[(size_t)step * (BB * DD) + b * DD + t] = h;
        }
        __syncthreads();                             // B4
    }
}

// ---------------------------------------------------------------------------
extern "C" void kernel_launch(void* const* d_in, const int* in_sizes, int n_in,
                              void* d_out, int out_size) {
    const float* enc  = (const float*)d_in[0];
    const float* W1_w = (const float*)d_in[1];
    const float* W1_b = (const float*)d_in[2];
    const float* W2_w = (const float*)d_in[3];
    const float* W2_b = (const float*)d_in[4];
    const float* W_ih = (const float*)d_in[5];
    const float* W_hh = (const float*)d_in[6];
    const float* b_ih = (const float*)d_in[7];
    const float* b_hh = (const float*)d_in[8];
    float* out = (float*)d_out;

    prep_kernel<<<129, 256>>>(W1_w, W_hh, b_ih, b_hh);
    decoder_kernel<<<BB, 512>>>(enc, W1_b, W2_w, W2_b, W_ih, out);
}

// round 6
// speedup vs baseline: 1.8148x; 1.8148x over previous
#include <cuda_runtime.h>
#include <cuda_fp16.h>

#define BB 256   // batch
#define SS 256   // seq len / steps
#define DD 128   // decoder dim
#define GG 512   // 4*D gates
#define TN 1024  // lookup-table intervals (nodes = TN+1)

// fp16x2-packed LSTM hidden weights, warp-coalesced block layout:
// uint4 block (j,u): j=0..15 (k-range [8j,8j+8)), u=0..511 (gate).
// word m of block = half2{ W_hh[u][8j+2m], W_hh[u][8j+2m+1] }.
// flat uint index = (j*512 + u)*4 + m.  Total 128 KB -> L1-resident.
__device__ __align__(16) unsigned int g_Wpack[32768];
__device__ float g_w1sum[SS];
__device__ float g_bias[GG];

__device__ __forceinline__ float tanh_fast(float x) {
    float y;
    asm("tanh.approx.f32 %0, %1;" : "=f"(y) : "f"(x));
    return y;
}
__device__ __forceinline__ float sigmoid_fast(float x) {
    return fmaf(tanh_fast(0.5f * x), 0.5f, 0.5f);
}
__device__ __forceinline__ unsigned long long pack2(float a, float b) {
    unsigned long long r;
    asm("mov.b64 %0, {%1,%2};" : "=l"(r) : "f"(a), "f"(b));
    return r;
}

// ---------------------------------------------------------------------------
// Prep kernel: pack W_hh to fp16 blocks, row-sum W1_w, fuse biases. One-time.
// ---------------------------------------------------------------------------
__global__ void prep_kernel(const float* __restrict__ W1_w,
                            const float* __restrict__ W_hh,
                            const float* __restrict__ b_ih,
                            const float* __restrict__ b_hh) {
    int blk = blockIdx.x;
    int t = threadIdx.x;
    if (blk < 128) {
        int idx = blk * 256 + t;          // 0..32767
        int j = idx >> 11;                // k-block 0..15
        int u = (idx >> 2) & 511;         // gate
        int m = idx & 3;
        int k0 = 8 * j + 2 * m;
        __half2 v = __halves2half2(__float2half_rn(W_hh[u * DD + k0]),
                                   __float2half_rn(W_hh[u * DD + k0 + 1]));
        g_Wpack[idx] = *(unsigned int*)&v;
    } else {
        int lane = t & 31, w = t >> 5;
        for (int r = 0; r < 32; r++) {
            int s = w * 32 + r;
            float acc = 0.f;
            #pragma unroll
            for (int i = 0; i < 8; i++) acc += W1_w[s * SS + lane + 32 * i];
            #pragma unroll
            for (int off = 16; off; off >>= 1)
                acc += __shfl_xor_sync(0xffffffffu, acc, off);
            if (lane == 0) g_w1sum[s] = acc;
        }
        g_bias[t]       = b_ih[t]       + b_hh[t];
        g_bias[t + 256] = b_ih[t + 256] + b_hh[t + 256];
    }
}

// ---------------------------------------------------------------------------
// Main kernel: one CTA per batch element, 512 threads, 256 LSTM steps.
// Attention is collapsed to a per-CTA 1-D lookup table g(h) built once:
//   g(h) = (sum_s w_s(h) * e_s) / (sum_s w_s(h)),  w_s = exp(tanh(a_s + h*c_s))
// then ctx = (1/128) * sum_d g(h_d) each step.
// ---------------------------------------------------------------------------
__global__ __launch_bounds__(512, 2)
void decoder_kernel(const float* __restrict__ enc,   // [B,S,E]
                    const float* __restrict__ W1_b,  // [S]
                    const float* __restrict__ W2_w,  // [S,2S]
                    const float* __restrict__ W2_b,  // [S]
                    const float* __restrict__ W_ih,  // [4D,E]
                    float* __restrict__ out)         // [S,B,D]
{
    __shared__ __align__(16) float4 sAC[128];    // pair p: {a(2p),a(2p+1),c(2p),c(2p+1)}
    __shared__ __align__(16) float4 sE[128];     // pair p: {e0(2p),e0(2p+1),e1(2p),e1(2p+1)}
    __shared__ __align__(16) float  ebuf[2 * SS];
    __shared__ float a_st[SS];
    __shared__ __align__(16) float2 Graw[TN + 1];  // raw g at nodes
    __shared__ __align__(16) float4 T[TN];         // {g0,g1,dg0,dg1} per interval
    __shared__ float gates_s[GG];
    __shared__ __align__(16) float h_s[DD];
    __shared__ float c_s[DD];
    __shared__ __align__(16) float2 wred[4];

    const int b = blockIdx.x;
    const int t = threadIdx.x;       // 0..511
    const int lane = t & 31;
    const int warp = t >> 5;

    // ---- per-b init ----
    ebuf[t] = enc[b * (2 * SS) + t];
    if (t < DD) { h_s[t] = 0.f; c_s[t] = 0.f; }
    __syncthreads();

    // a[s] = encflat . W2_w[s,:] + W2_b[s] + W1_b[s]; 16 warps x 16 rows
    {
        const float4* W2w4 = (const float4*)W2_w;
        const float4* e4   = (const float4*)ebuf;
        for (int r = 0; r < 16; r++) {
            int s = warp * 16 + r;
            float acc = 0.f;
            #pragma unroll
            for (int i = 0; i < 4; i++) {
                float4 wv = W2w4[s * 128 + lane + 32 * i];
                float4 ev = e4[lane + 32 * i];
                acc += wv.x * ev.x + wv.y * ev.y + wv.z * ev.z + wv.w * ev.w;
            }
            #pragma unroll
            for (int off = 16; off; off >>= 1)
                acc += __shfl_xor_sync(0xffffffffu, acc, off);
            if (lane == 0) a_st[s] = acc + W2_b[s] + W1_b[s];
        }
    }
    __syncthreads();
    if (t < 128) {
        int p = t;
        sAC[p] = make_float4(a_st[2 * p], a_st[2 * p + 1],
                             g_w1sum[2 * p], g_w1sum[2 * p + 1]);
        sE[p]  = make_float4(ebuf[4 * p], ebuf[4 * p + 2],
                             ebuf[4 * p + 1], ebuf[4 * p + 3]);
    }
    __syncthreads();

    // Degree-5 Chebyshev-economized poly for exp(t), t in [-1,1], abs err <= 5e-5
    const unsigned long long P5 = pack2(0.00868688f, 0.00868688f);
    const unsigned long long P4 = pack2(0.04379392f, 0.04379392f);
    const unsigned long long P3 = pack2(0.16648880f, 0.16648880f);
    const unsigned long long P2 = pack2(0.49919676f, 0.49919676f);
    const unsigned long long P1 = pack2(1.00002231f, 1.00002231f);
    const unsigned long long P0 = pack2(1.00004478f, 1.00004478f);

    // ---- build lookup table: nodes k = 0..TN, h = -1 + k/(TN/2) ----
    {
        const double2* pAC = (const double2*)sAC;
        const double2* pE  = (const double2*)sE;
        for (int k = t; k < TN + 1; k += 512) {
            float h = fmaf((float)k, 2.0f / TN, -1.0f);
            unsigned long long hd2;
            asm("mov.b64 %0, {%1,%1};" : "=l"(hd2) : "f"(h));
            unsigned long long Z2 = 0ull, n02 = 0ull, n12 = 0ull;
            #pragma unroll 4
            for (int i = 0; i < 128; i++) {
                double2 acd = pAC[i];
                double2 eed = pE[i];
                unsigned long long ap  = __double_as_longlong(acd.x);
                unsigned long long cp  = __double_as_longlong(acd.y);
                unsigned long long e0p = __double_as_longlong(eed.x);
                unsigned long long e1p = __double_as_longlong(eed.y);
                unsigned long long x2;
                asm("fma.rn.f32x2 %0, %1, %2, %3;" : "=l"(x2) : "l"(hd2), "l"(cp), "l"(ap));
                float x0, x1;
                asm("mov.b64 {%0,%1}, %2;" : "=f"(x0), "=f"(x1) : "l"(x2));
                float t0 = tanh_fast(x0);
                float t1 = tanh_fast(x1);
                unsigned long long t2;
                asm("mov.b64 %0, {%1,%2};" : "=l"(t2) : "f"(t0), "f"(t1));
                unsigned long long p;
                asm("fma.rn.f32x2 %0, %1, %2, %3;" : "=l"(p) : "l"(P5), "l"(t2), "l"(P4));
                asm("fma.rn.f32x2 %0, %0, %1, %2;" : "+l"(p) : "l"(t2), "l"(P3));
                asm("fma.rn.f32x2 %0, %0, %1, %2;" : "+l"(p) : "l"(t2), "l"(P2));
                asm("fma.rn.f32x2 %0, %0, %1, %2;" : "+l"(p) : "l"(t2), "l"(P1));
                asm("fma.rn.f32x2 %0, %0, %1, %2;" : "+l"(p) : "l"(t2), "l"(P0));
                asm("add.rn.f32x2 %0, %0, %1;"     : "+l"(Z2) : "l"(p));
                asm("fma.rn.f32x2 %0, %1, %2, %0;" : "+l"(n02) : "l"(p), "l"(e0p));
                asm("fma.rn.f32x2 %0, %1, %2, %0;" : "+l"(n12) : "l"(p), "l"(e1p));
            }
            float Zl, Zh, a0, a1, b0, b1;
            asm("mov.b64 {%0,%1}, %2;" : "=f"(Zl), "=f"(Zh) : "l"(Z2));
            asm("mov.b64 {%0,%1}, %2;" : "=f"(a0), "=f"(a1) : "l"(n02));
            asm("mov.b64 {%0,%1}, %2;" : "=f"(b0), "=f"(b1) : "l"(n12));
            float Z = Zl + Zh, n0 = a0 + a1, n1 = b0 + b1;
            float inv = __fdividef(1.f, Z);
            Graw[k] = make_float2(n0 * inv, n1 * inv);
        }
    }
    __syncthreads();
    for (int k = t; k < TN; k += 512) {
        float2 g0 = Graw[k];
        float2 g1 = Graw[k + 1];
        T[k] = make_float4(g0.x, g0.y, g1.x - g0.x, g1.y - g0.y);
    }
    __syncthreads();

    // thread roles
    const float bias = g_bias[t];     // LSTM: one gate per thread
    const float wih0 = W_ih[2 * t + 0];
    const float wih1 = W_ih[2 * t + 1];
    const uint4* Wq4 = ((const uint4*)g_Wpack) + t;   // + j*512 per k-block

    for (int step = 0; step < SS; step++) {
        // ---- LSTM h-dot (depends only on previous h) ----
        float acc0 = bias, acc1 = 0.f;
        {
            const float4* h4 = (const float4*)h_s;
            #pragma unroll 4
            for (int j = 0; j < 16; j++) {
                uint4 wr = Wq4[j * 512];            // LDG.128, L1-resident
                float4 hA = h4[2 * j];              // broadcast LDS.128
                float4 hB = h4[2 * j + 1];
                float2 f0 = __half22float2(*(const __half2*)&wr.x);
                float2 f1 = __half22float2(*(const __half2*)&wr.y);
                float2 f2 = __half22float2(*(const __half2*)&wr.z);
                float2 f3 = __half22float2(*(const __half2*)&wr.w);
                acc0 = fmaf(hA.x, f0.x, acc0);
                acc1 = fmaf(hA.y, f0.y, acc1);
                acc0 = fmaf(hA.z, f1.x, acc0);
                acc1 = fmaf(hA.w, f1.y, acc1);
                acc0 = fmaf(hB.x, f2.x, acc0);
                acc1 = fmaf(hB.y, f2.y, acc1);
                acc0 = fmaf(hB.z, f3.x, acc0);
                acc1 = fmaf(hB.w, f3.y, acc1);
            }
        }
        float acc = acc0 + acc1;

        // ---- attention via table lookup (threads 0..127, one per d) ----
        if (t < 128) {
            float h = h_s[t];
            float u = fmaf(h, (float)(TN / 2), (float)(TN / 2));
            int i = (int)u;
            i = max(0, min(i, TN - 1));
            float f = u - (float)i;
            float4 tv = T[i];
            float gx = fmaf(f, tv.z, tv.x);
            float gy = fmaf(f, tv.w, tv.y);
            #pragma unroll
            for (int off = 16; off; off >>= 1) {
                gx += __shfl_xor_sync(0xffffffffu, gx, off);
                gy += __shfl_xor_sync(0xffffffffu, gy, off);
            }
            if (lane == 0) wred[warp] = make_float2(gx, gy);
        }
        __syncthreads();                             // B1

        float2 r0 = wred[0], r1 = wred[1], r2 = wred[2], r3 = wred[3];
        const float x0c = (r0.x + r1.x + r2.x + r3.x) * (1.f / 128.f);
        const float x1c = (r0.y + r1.y + r2.y + r3.y) * (1.f / 128.f);

        acc = fmaf(x0c, wih0, fmaf(x1c, wih1, acc));
        gates_s[t] = acc;
        __syncthreads();                             // B2

        // ---- c/h update + output ----
        if (t < DD) {
            float gi = gates_s[t];
            float gf = gates_s[t + 128];
            float gg = gates_s[t + 256];
            float go = gates_s[t + 384];
            float si = sigmoid_fast(gi);
            float sf = sigmoid_fast(gf);
            float so = sigmoid_fast(go);
            float c = fmaf(sf, c_s[t], si * tanh_fast(gg));
            float h = so * tanh_fast(c);
            c_s[t] = c;
            h_s[t] = h;
            out[(size_t)step * (BB * DD) + b * DD + t] = h;
        }
        __syncthreads();                             // B3
    }
}

// ---------------------------------------------------------------------------
extern "C" void kernel_launch(void* const* d_in, const int* in_sizes, int n_in,
                              void* d_out, int out_size) {
    const float* enc  = (const float*)d_in[0];
    const float* W1_w = (const float*)d_in[1];
    const float* W1_b = (const float*)d_in[2];
    const float* W2_w = (const float*)d_in[3];
    const float* W2_b = (const float*)d_in[4];
    const float* W_ih = (const float*)d_in[5];
    const float* W_hh = (const float*)d_in[6];
    const float* b_ih = (const float*)d_in[7];
    const float* b_hh = (const float*)d_in[8];
    float* out = (float*)d_out;

    prep_kernel<<<129, 256>>>(W1_w, W_hh, b_ih, b_hh);
    decoder_kernel<<<BB, 512>>>(enc, W1_b, W2_w, W2_b, W_ih, out);
}